// round 6
// baseline (speedup 1.0000x reference)
#include <cuda_runtime.h>
#include <cuda_bf16.h>
#include <math.h>

// Problem constants
#define NN 512
#define DIM 384
#define PDIM 128
#define H 8
#define SK 16
#define SV 16
#define PK 4
#define PV 8
#define PROJ_COLS 768           // 128+128+128+96+96+192
#define RES_COLS 1408           // 128 + 192 + 64 + 1024
#define EPSV 1e-8f

__device__ __constant__ float kScaleScalar = 0.14433756729740643f;  // (3*16)^-0.5
__device__ __constant__ float kScalePoint  = 0.13608276348795434f;  // (3*4*4.5)^-0.5
__device__ __constant__ float kScalePair   = 0.57735026918962576f;  // 3^-0.5

// Scratch (allocation-free contract: __device__ globals)
__device__ float g_Wcat[DIM * PROJ_COLS];
__device__ float g_proj[NN * PROJ_COLS];
__device__ float g_qpg[NN * H * PK * 3];
__device__ float g_kpg[NN * H * PK * 3];
__device__ float g_vpg[NN * H * PV * 3];
__device__ float g_res[NN * RES_COLS];

// ---------------------------------------------------------------------------
// Kernel 1: concat projection weights into [384 x 768]
// ---------------------------------------------------------------------------
__global__ void concat_w_kernel(const float* __restrict__ Wsq, const float* __restrict__ Wsk,
                                const float* __restrict__ Wsv, const float* __restrict__ Wpq,
                                const float* __restrict__ Wpk, const float* __restrict__ Wpv)
{
    int idx = blockIdx.x * blockDim.x + threadIdx.x;
    if (idx >= DIM * PROJ_COLS) return;
    int k = idx / PROJ_COLS;
    int c = idx - k * PROJ_COLS;
    float v;
    if (c < 128)       v = Wsq[k * 128 + c];
    else if (c < 256)  v = Wsk[k * 128 + (c - 128)];
    else if (c < 384)  v = Wsv[k * 128 + (c - 256)];
    else if (c < 480)  v = Wpq[k * 96 + (c - 384)];
    else if (c < 576)  v = Wpk[k * 96 + (c - 480)];
    else               v = Wpv[k * 192 + (c - 576)];
    g_Wcat[idx] = v;
}

// ---------------------------------------------------------------------------
// 64x64 tiled fp32 GEMM, 4x4 microtile, BK=16.  C (+)= A[M,K] * B[K,N].
// ---------------------------------------------------------------------------
__global__ __launch_bounds__(256) void gemm64_kernel(const float* __restrict__ A,
                                                     const float* __restrict__ B,
                                                     float* __restrict__ C,
                                                     int M, int N, int K,
                                                     int kChunk, int useAtomic)
{
    __shared__ float As[16][68];   // [k][m]
    __shared__ float Bs[16][68];   // [k][n]
    const int bm = blockIdx.y * 64;
    const int bn = blockIdx.x * 64;
    int k0 = blockIdx.z * kChunk;
    int k1 = k0 + kChunk; if (k1 > K) k1 = K;
    const int t  = threadIdx.x;
    const int tx = t & 15, ty = t >> 4;

    const int lm  = t >> 2;          // A row 0..63
    const int lk4 = (t & 3) * 4;     // A k offset 0,4,8,12
    const int lkb = t >> 4;          // B k row 0..15
    const int lnb = (t & 15) * 4;    // B n offset

    float acc[4][4];
    #pragma unroll
    for (int r = 0; r < 4; r++)
        #pragma unroll
        for (int c = 0; c < 4; c++) acc[r][c] = 0.f;

    for (int kt = k0; kt < k1; kt += 16) {
        float4 a4 = *(const float4*)&A[(size_t)(bm + lm) * K + kt + lk4];
        float4 b4 = *(const float4*)&B[(size_t)(kt + lkb) * N + bn + lnb];
        __syncthreads();
        As[lk4 + 0][lm] = a4.x; As[lk4 + 1][lm] = a4.y;
        As[lk4 + 2][lm] = a4.z; As[lk4 + 3][lm] = a4.w;
        *(float4*)&Bs[lkb][lnb] = b4;
        __syncthreads();
        #pragma unroll
        for (int kk = 0; kk < 16; kk++) {
            float4 av = *(const float4*)&As[kk][ty * 4];
            float4 bv = *(const float4*)&Bs[kk][tx * 4];
            acc[0][0] += av.x * bv.x; acc[0][1] += av.x * bv.y; acc[0][2] += av.x * bv.z; acc[0][3] += av.x * bv.w;
            acc[1][0] += av.y * bv.x; acc[1][1] += av.y * bv.y; acc[1][2] += av.y * bv.z; acc[1][3] += av.y * bv.w;
            acc[2][0] += av.z * bv.x; acc[2][1] += av.z * bv.y; acc[2][2] += av.z * bv.z; acc[2][3] += av.z * bv.w;
            acc[3][0] += av.w * bv.x; acc[3][1] += av.w * bv.y; acc[3][2] += av.w * bv.z; acc[3][3] += av.w * bv.w;
        }
    }
    #pragma unroll
    for (int r = 0; r < 4; r++) {
        float* cp = &C[(size_t)(bm + ty * 4 + r) * N + bn + tx * 4];
        if (useAtomic) {
            atomicAdd(cp + 0, acc[r][0]); atomicAdd(cp + 1, acc[r][1]);
            atomicAdd(cp + 2, acc[r][2]); atomicAdd(cp + 3, acc[r][3]);
        } else {
            float4 v; v.x = acc[r][0]; v.y = acc[r][1]; v.z = acc[r][2]; v.w = acc[r][3];
            *(float4*)cp = v;
        }
    }
}

// ---------------------------------------------------------------------------
// Kernel 3: rotate+translate point projections to global frame.
// ---------------------------------------------------------------------------
__global__ void transform_kernel(const float* __restrict__ rot, const float* __restrict__ trans)
{
    int pid = blockIdx.x * blockDim.x + threadIdx.x;
    if (pid >= 65536) return;
    int n;
    const float* src;
    float* dst;
    if (pid < 16384) {
        n = pid >> 5; int pd = pid & 31;
        src = g_proj + n * PROJ_COLS + 384 + pd * 3;
        dst = g_qpg + n * 96 + pd * 3;
    } else if (pid < 32768) {
        int p = pid - 16384;
        n = p >> 5; int pd = p & 31;
        src = g_proj + n * PROJ_COLS + 480 + pd * 3;
        dst = g_kpg + n * 96 + pd * 3;
    } else {
        int p = pid - 32768;
        n = p >> 6; int pd = p & 63;
        src = g_proj + n * PROJ_COLS + 576 + pd * 3;
        dst = g_vpg + n * 192 + pd * 3;
    }
    float p0 = src[0], p1 = src[1], p2 = src[2];
    const float* R = rot + n * 9;
    const float* tt = trans + n * 3;
    dst[0] = p0 * R[0] + p1 * R[3] + p2 * R[6] + tt[0];
    dst[1] = p0 * R[1] + p1 * R[4] + p2 * R[7] + tt[1];
    dst[2] = p0 * R[2] + p1 * R[5] + p2 * R[8] + tt[2];
}

// ---------------------------------------------------------------------------
// Kernel 4: fused two-pass attention, one block per query i.
//   Phase A: all logits into sLogit[8][512]  (float4 smem, Wpair in regs)
//   Phase B: softmax per head (warp per head), normalized weights in sLogit
//   Phase C: res_pair (coalesced float4 global re-read) + res_scalar/point
//   Phase D: epilogue (R^T back-transform, norms), write results row [1408]
// ---------------------------------------------------------------------------
__global__ __launch_bounds__(256) void attn_kernel(const float* __restrict__ pairw,
                                                   const float* __restrict__ rot,
                                                   const float* __restrict__ trans,
                                                   const float* __restrict__ point_weights,
                                                   const float* __restrict__ Wpair,
                                                   const float* __restrict__ bpair)
{
    const int i = blockIdx.x;
    const int t = threadIdx.x;
    const int w = t >> 5, lane = t & 31;
    const int h = lane >> 2, s = lane & 3;

    __shared__ float  sLogit[H][NN];         // 16 KB: logits -> softmax weights
    __shared__ float4 sPair4[32][33];        // 16.9 KB: 32-j pair tile (padded)
    __shared__ float  sAccVs[H][SV];
    __shared__ float  sAccVp[H][PV * 3];

    // --- register-resident per-(h,s) data; lane owns contiguous d in [32s, 32s+32) ---
    float4 Wreg[8];
    #pragma unroll
    for (int k = 0; k < 8; k++) {
        int d0 = s * 32 + 4 * k;
        Wreg[k].x = Wpair[(d0 + 0) * 8 + h];
        Wreg[k].y = Wpair[(d0 + 1) * 8 + h];
        Wreg[k].z = Wpair[(d0 + 2) * 8 + h];
        Wreg[k].w = Wpair[(d0 + 3) * 8 + h];
    }
    const float4 qs4 = *(const float4*)&g_proj[i * PROJ_COLS + h * 16 + 4 * s];
    const float qp0 = g_qpg[i * 96 + h * 12 + 3 * s + 0];
    const float qp1 = g_qpg[i * 96 + h * 12 + 3 * s + 1];
    const float qp2 = g_qpg[i * 96 + h * 12 + 3 * s + 2];
    const float spw = log1pf(__expf(point_weights[h]));
    const float cP = -0.5f * spw * kScalePoint;
    const float biasH = bpair[h] * kScalePair;

    const float* pairRow = pairw + (size_t)i * NN * PDIM;

    // ---- Phase A: logits ----
    for (int jt = 0; jt < NN; jt += 32) {
        __syncthreads();
        {   // stage 32 x 128 floats as float4 (coalesced)
            int jj = t >> 3, q4 = t & 7;
            const float4* src = (const float4*)(pairRow + (size_t)(jt + jj) * PDIM);
            #pragma unroll
            for (int k2 = 0; k2 < 4; k2++)
                sPair4[jj][q4 + 8 * k2] = src[q4 + 8 * k2];
        }
        __syncthreads();
        #pragma unroll
        for (int u = 0; u < 4; u++) {
            const int jj = (w << 2) + u;
            const int j = jt + jj;
            const float4* pr = &sPair4[jj][s * 8];
            float accB = 0.f;
            #pragma unroll
            for (int k = 0; k < 8; k++) {
                float4 p = pr[k];
                accB += p.x * Wreg[k].x + p.y * Wreg[k].y
                      + p.z * Wreg[k].z + p.w * Wreg[k].w;
            }
            const float4 ks4 = *(const float4*)&g_proj[j * PROJ_COLS + 128 + h * 16 + 4 * s];
            float accS = qs4.x * ks4.x + qs4.y * ks4.y + qs4.z * ks4.z + qs4.w * ks4.w;
            const float* kp = &g_kpg[j * 96 + h * 12 + 3 * s];
            float d0 = qp0 - kp[0], d1 = qp1 - kp[1], d2 = qp2 - kp[2];
            float accPt = d0 * d0 + d1 * d1 + d2 * d2;
            float part = accB * kScalePair + accS * kScaleScalar + accPt * cP;
            part += __shfl_xor_sync(0xffffffffu, part, 1);
            part += __shfl_xor_sync(0xffffffffu, part, 2);
            if (s == 0) sLogit[h][j] = part + biasH;
        }
    }
    __syncthreads();

    // ---- Phase B: softmax (warp w handles head w), weights normalized in place ----
    {
        float m = -1e30f;
        for (int j = lane; j < NN; j += 32) m = fmaxf(m, sLogit[w][j]);
        #pragma unroll
        for (int o = 16; o; o >>= 1) m = fmaxf(m, __shfl_xor_sync(0xffffffffu, m, o));
        float sum = 0.f;
        for (int j = lane; j < NN; j += 32) {
            float e = __expf(sLogit[w][j] - m);
            sLogit[w][j] = e;
            sum += e;
        }
        #pragma unroll
        for (int o = 16; o; o >>= 1) sum += __shfl_xor_sync(0xffffffffu, sum, o);
        float inv = 1.f / sum;
        for (int j = lane; j < NN; j += 32) sLogit[w][j] *= inv;
    }
    __syncthreads();

    float* resRow = g_res + (size_t)i * RES_COLS;

    // ---- Phase C part 1: res_pair.  t = h2*32 + d4, one float4 per thread.
    // Warp loads are fully coalesced (512B); the 8 head-warps hit L1 on reuse.
    {
        const int h2 = t >> 5, d4 = t & 31;
        float4 acc = make_float4(0.f, 0.f, 0.f, 0.f);
        const float4* pc = (const float4*)pairRow + d4;
        const float* wp = &sLogit[h2][0];
        #pragma unroll 4
        for (int j = 0; j < NN; j++) {
            float wg = wp[j];
            float4 p = pc[(size_t)j * 32];
            acc.x += wg * p.x; acc.y += wg * p.y;
            acc.z += wg * p.z; acc.w += wg * p.w;
        }
        *((float4*)(resRow + 384 + h2 * 128) + d4) = acc;
    }

    // ---- Phase C parts 2+3: res_scalar + res_point (L2-resident v data) ----
    for (int c = t; c < 320; c += 256) {
        float acc = 0.f;
        if (c < 128) {
            int hh = c >> 4, d = c & 15;
            const float* vsr = g_proj + 256 + hh * SV + d;
            const float* wp = &sLogit[hh][0];
            #pragma unroll 4
            for (int j = 0; j < NN; j++) acc += wp[j] * vsr[(size_t)j * PROJ_COLS];
            sAccVs[hh][d] = acc;
        } else {
            int c2 = c - 128;
            int hh = c2 / 24, k = c2 % 24;
            const float* vpr = g_vpg + hh * 24 + k;
            const float* wp = &sLogit[hh][0];
            #pragma unroll 4
            for (int j = 0; j < NN; j++) acc += wp[j] * vpr[(size_t)j * 192];
            sAccVp[hh][k] = acc;
        }
    }
    __syncthreads();

    // ---- Phase D: epilogue ----
    if (t < 128) resRow[t] = sAccVs[t >> 4][t & 15];                  // scalar @ 0
    if (t < 64) {                                                     // points @ 128, norms @ 320
        int hh = t >> 3, d = t & 7;
        float t0 = trans[i * 3 + 0], t1 = trans[i * 3 + 1], t2 = trans[i * 3 + 2];
        float g0 = sAccVp[hh][d * 3 + 0] - t0;
        float g1 = sAccVp[hh][d * 3 + 1] - t1;
        float g2 = sAccVp[hh][d * 3 + 2] - t2;
        const float* R = rot + i * 9;
        float n2 = EPSV;
        #pragma unroll
        for (int r = 0; r < 3; r++) {
            float lr = g0 * R[r * 3 + 0] + g1 * R[r * 3 + 1] + g2 * R[r * 3 + 2];
            resRow[128 + hh * 24 + d * 3 + r] = lr;
            n2 += lr * lr;
        }
        resRow[320 + hh * 8 + d] = sqrtf(n2);
    }
}

// ---------------------------------------------------------------------------
// Kernel 5: init output with bias
// ---------------------------------------------------------------------------
__global__ void init_out_kernel(float* __restrict__ out, const float* __restrict__ bout)
{
    int idx = blockIdx.x * blockDim.x + threadIdx.x;
    if (idx < NN * DIM) out[idx] = bout[idx % DIM];
}

// ---------------------------------------------------------------------------
extern "C" void kernel_launch(void* const* d_in, const int* in_sizes, int n_in,
                              void* d_out, int out_size)
{
    const float* x      = (const float*)d_in[0];
    const float* pairw  = (const float*)d_in[1];
    const float* rot    = (const float*)d_in[2];
    const float* trans  = (const float*)d_in[3];
    const float* Wsq    = (const float*)d_in[4];
    const float* Wsk    = (const float*)d_in[5];
    const float* Wsv    = (const float*)d_in[6];
    const float* Wpq    = (const float*)d_in[7];
    const float* Wpk    = (const float*)d_in[8];
    const float* Wpv    = (const float*)d_in[9];
    const float* pw     = (const float*)d_in[10];
    const float* Wpair  = (const float*)d_in[11];
    const float* bpair  = (const float*)d_in[12];
    const float* Wout   = (const float*)d_in[13];
    const float* bout   = (const float*)d_in[14];
    float* out = (float*)d_out;

    float *pWcat, *pProj, *pRes;
    cudaGetSymbolAddress((void**)&pWcat, g_Wcat);
    cudaGetSymbolAddress((void**)&pProj, g_proj);
    cudaGetSymbolAddress((void**)&pRes,  g_res);

    // 1. concat weights
    concat_w_kernel<<<(DIM * PROJ_COLS + 255) / 256, 256>>>(Wsq, Wsk, Wsv, Wpq, Wpk, Wpv);

    // 2. projections: proj[512,768] = x[512,384] @ Wcat[384,768]
    gemm64_kernel<<<dim3(PROJ_COLS / 64, NN / 64, 1), 256>>>(x, pWcat, pProj,
                                                             NN, PROJ_COLS, DIM, DIM, 0);

    // 3. transform points to global frame
    transform_kernel<<<65536 / 256, 256>>>(rot, trans);

    // 4. fused two-pass attention
    attn_kernel<<<NN, 256>>>(pairw, rot, trans, pw, Wpair, bpair);

    // 5. init output with bias
    init_out_kernel<<<(NN * DIM + 255) / 256, 256>>>(out, bout);

    // 6. out += res[512,1408] @ Wout[1408,384], split-K=4 with atomics
    gemm64_kernel<<<dim3(DIM / 64, NN / 64, 4), 256>>>(pRes, Wout, out,
                                                       NN, DIM, RES_COLS, 352, 1);
}

// round 7
// speedup vs baseline: 1.6637x; 1.6637x over previous
#include <cuda_runtime.h>
#include <cuda_bf16.h>
#include <math.h>

// Problem constants
#define NN 512
#define DIM 384
#define PDIM 128
#define H 8
#define SK 16
#define SV 16
#define PK 4
#define PV 8
#define PROJ_COLS 768           // 128+128+128+96+96+192
#define RES_COLS 1408           // 128 + 192 + 64 + 1024
#define EPSV 1e-8f
#define LPITCH 516              // sLogit row pitch (floats): (4h+j)%32 distinct, 16B-aligned

__device__ __constant__ float kScaleScalar = 0.14433756729740643f;  // (3*16)^-0.5
__device__ __constant__ float kScalePoint  = 0.13608276348795434f;  // (3*4*4.5)^-0.5
__device__ __constant__ float kScalePair   = 0.57735026918962576f;  // 3^-0.5

// Scratch (allocation-free contract: __device__ globals)
__device__ float g_Wcat[DIM * PROJ_COLS];
__device__ float g_proj[NN * PROJ_COLS];
__device__ float g_qpg[NN * H * PK * 3];      // global q points [n][h*12+3s+c]
__device__ float g_kpg[NN * H * PK * 3];      // global k points
__device__ float g_vpT[H * PV * 3 * NN];      // TRANSPOSED global v points [row=3*pd+c][n]
__device__ float g_vsT[H * SV * NN];          // TRANSPOSED scalar v [d][n]
__device__ float g_lp[NN * H * NN];           // pair logits [i][h][j] (bias+scale folded)
__device__ float g_attn[NN * H * NN];         // normalized attn weights [i][h][j]
__device__ float g_res[NN * RES_COLS];

// ---------------------------------------------------------------------------
// Kernel 1: concat projection weights into [384 x 768]
// ---------------------------------------------------------------------------
__global__ void concat_w_kernel(const float* __restrict__ Wsq, const float* __restrict__ Wsk,
                                const float* __restrict__ Wsv, const float* __restrict__ Wpq,
                                const float* __restrict__ Wpk, const float* __restrict__ Wpv)
{
    int idx = blockIdx.x * blockDim.x + threadIdx.x;
    if (idx >= DIM * PROJ_COLS) return;
    int k = idx / PROJ_COLS;
    int c = idx - k * PROJ_COLS;
    float v;
    if (c < 128)       v = Wsq[k * 128 + c];
    else if (c < 256)  v = Wsk[k * 128 + (c - 128)];
    else if (c < 384)  v = Wsv[k * 128 + (c - 256)];
    else if (c < 480)  v = Wpq[k * 96 + (c - 384)];
    else if (c < 576)  v = Wpk[k * 96 + (c - 480)];
    else               v = Wpv[k * 192 + (c - 576)];
    g_Wcat[idx] = v;
}

// ---------------------------------------------------------------------------
// 64x64 tiled fp32 GEMM, 4x4 microtile, BK=16.  C = A[M,K]*B[K,N] (+ bias[n]).
// ---------------------------------------------------------------------------
__global__ __launch_bounds__(256) void gemm64_kernel(const float* __restrict__ A,
                                                     const float* __restrict__ B,
                                                     float* __restrict__ C,
                                                     const float* __restrict__ bias,
                                                     int M, int N, int K)
{
    __shared__ float As[16][68];   // [k][m]
    __shared__ float Bs[16][68];   // [k][n]
    const int bm = blockIdx.y * 64;
    const int bn = blockIdx.x * 64;
    const int t  = threadIdx.x;
    const int tx = t & 15, ty = t >> 4;

    const int lm  = t >> 2;          // A row 0..63
    const int lk4 = (t & 3) * 4;     // A k offset 0,4,8,12
    const int lkb = t >> 4;          // B k row 0..15
    const int lnb = (t & 15) * 4;    // B n offset

    float acc[4][4];
    #pragma unroll
    for (int r = 0; r < 4; r++)
        #pragma unroll
        for (int c = 0; c < 4; c++) acc[r][c] = 0.f;

    for (int kt = 0; kt < K; kt += 16) {
        float4 a4 = *(const float4*)&A[(size_t)(bm + lm) * K + kt + lk4];
        float4 b4 = *(const float4*)&B[(size_t)(kt + lkb) * N + bn + lnb];
        __syncthreads();
        As[lk4 + 0][lm] = a4.x; As[lk4 + 1][lm] = a4.y;
        As[lk4 + 2][lm] = a4.z; As[lk4 + 3][lm] = a4.w;
        *(float4*)&Bs[lkb][lnb] = b4;
        __syncthreads();
        #pragma unroll
        for (int kk = 0; kk < 16; kk++) {
            float4 av = *(const float4*)&As[kk][ty * 4];
            float4 bv = *(const float4*)&Bs[kk][tx * 4];
            acc[0][0] += av.x * bv.x; acc[0][1] += av.x * bv.y; acc[0][2] += av.x * bv.z; acc[0][3] += av.x * bv.w;
            acc[1][0] += av.y * bv.x; acc[1][1] += av.y * bv.y; acc[1][2] += av.y * bv.z; acc[1][3] += av.y * bv.w;
            acc[2][0] += av.z * bv.x; acc[2][1] += av.z * bv.y; acc[2][2] += av.z * bv.z; acc[2][3] += av.z * bv.w;
            acc[3][0] += av.w * bv.x; acc[3][1] += av.w * bv.y; acc[3][2] += av.w * bv.z; acc[3][3] += av.w * bv.w;
        }
    }
    float4 bv = make_float4(0.f, 0.f, 0.f, 0.f);
    if (bias) bv = *(const float4*)&bias[bn + tx * 4];
    #pragma unroll
    for (int r = 0; r < 4; r++) {
        float4 v;
        v.x = acc[r][0] + bv.x; v.y = acc[r][1] + bv.y;
        v.z = acc[r][2] + bv.z; v.w = acc[r][3] + bv.w;
        *(float4*)&C[(size_t)(bm + ty * 4 + r) * N + bn + tx * 4] = v;
    }
}

// ---------------------------------------------------------------------------
// Kernel 3: rotate+translate points to global frame; also build transposed
// v-point and v-scalar matrices for coalesced phase-C reductions.
// ---------------------------------------------------------------------------
__global__ void transform_kernel(const float* __restrict__ rot, const float* __restrict__ trans)
{
    int pid = blockIdx.x * blockDim.x + threadIdx.x;   // 131072 jobs
    if (pid >= 131072) return;
    if (pid < 16384) {                 // q points: 512*32
        int n = pid >> 5, pd = pid & 31;
        const float* src = g_proj + n * PROJ_COLS + 384 + pd * 3;
        float p0 = src[0], p1 = src[1], p2 = src[2];
        const float* R = rot + n * 9;
        const float* tt = trans + n * 3;
        float* dst = g_qpg + n * 96 + pd * 3;
        dst[0] = p0 * R[0] + p1 * R[3] + p2 * R[6] + tt[0];
        dst[1] = p0 * R[1] + p1 * R[4] + p2 * R[7] + tt[1];
        dst[2] = p0 * R[2] + p1 * R[5] + p2 * R[8] + tt[2];
    } else if (pid < 32768) {          // k points
        int p = pid - 16384;
        int n = p >> 5, pd = p & 31;
        const float* src = g_proj + n * PROJ_COLS + 480 + pd * 3;
        float p0 = src[0], p1 = src[1], p2 = src[2];
        const float* R = rot + n * 9;
        const float* tt = trans + n * 3;
        float* dst = g_kpg + n * 96 + pd * 3;
        dst[0] = p0 * R[0] + p1 * R[3] + p2 * R[6] + tt[0];
        dst[1] = p0 * R[1] + p1 * R[4] + p2 * R[7] + tt[1];
        dst[2] = p0 * R[2] + p1 * R[5] + p2 * R[8] + tt[2];
    } else if (pid < 65536) {          // v points: 512*64 -> transposed global
        int p = pid - 32768;
        int n = p >> 6, pd = p & 63;
        const float* src = g_proj + n * PROJ_COLS + 576 + pd * 3;
        float p0 = src[0], p1 = src[1], p2 = src[2];
        const float* R = rot + n * 9;
        const float* tt = trans + n * 3;
        g_vpT[(3 * pd + 0) * NN + n] = p0 * R[0] + p1 * R[3] + p2 * R[6] + tt[0];
        g_vpT[(3 * pd + 1) * NN + n] = p0 * R[1] + p1 * R[4] + p2 * R[7] + tt[1];
        g_vpT[(3 * pd + 2) * NN + n] = p0 * R[2] + p1 * R[5] + p2 * R[8] + tt[2];
    } else {                           // v scalar transpose: 512*128
        int e = pid - 65536;
        int n = e >> 7, d = e & 127;
        g_vsT[d * NN + n] = g_proj[n * PROJ_COLS + 256 + d];
    }
}

// ---------------------------------------------------------------------------
// Kernel 4: pair-bias logits.  g_lp[i][h][j] = (pair[i,j,:]@Wpair[:,h] + bpair[h]) * scale.
// Block per i; 32-j smem tiles; Wpair register-resident per (h,s) lane.
// Lane = h*4+s owns d in {16k+4s+c : k<8, c<4}; shfl-reduce over s.
// ---------------------------------------------------------------------------
__global__ __launch_bounds__(256) void pair_logits_kernel(const float* __restrict__ pairw,
                                                          const float* __restrict__ Wpair,
                                                          const float* __restrict__ bpair)
{
    const int i = blockIdx.x;
    const int t = threadIdx.x;
    const int w = t >> 5, lane = t & 31;
    const int h = lane >> 2, s = lane & 3;

    __shared__ float sPair[32 * 132];   // 32 j x 128 d, row pitch 132 floats
    __shared__ float sLP[H * LPITCH];   // logits [h][j]

    float4 Wreg[8];
    #pragma unroll
    for (int k = 0; k < 8; k++) {
        int d0 = 16 * k + 4 * s;
        Wreg[k].x = Wpair[(d0 + 0) * 8 + h];
        Wreg[k].y = Wpair[(d0 + 1) * 8 + h];
        Wreg[k].z = Wpair[(d0 + 2) * 8 + h];
        Wreg[k].w = Wpair[(d0 + 3) * 8 + h];
    }
    const float bph = bpair[h];
    const float* pairRow = pairw + (size_t)i * NN * PDIM;

    for (int jt = 0; jt < NN; jt += 32) {
        __syncthreads();
        #pragma unroll
        for (int m = 0; m < 4; m++) {       // stage 32x128 floats, coalesced
            int idx = t + 256 * m;          // 0..1023 float4 slots
            int jj = idx >> 5, c4 = idx & 31;
            *(float4*)&sPair[jj * 132 + 4 * c4] =
                *(const float4*)&pairRow[(size_t)(jt + jj) * PDIM + 4 * c4];
        }
        __syncthreads();
        #pragma unroll
        for (int u = 0; u < 4; u++) {
            int jj = (w << 2) + u;
            const float* pr = &sPair[jj * 132];
            float accB = 0.f;
            #pragma unroll
            for (int k = 0; k < 8; k++) {
                float4 p = *(const float4*)&pr[16 * k + 4 * s];
                accB += p.x * Wreg[k].x + p.y * Wreg[k].y
                      + p.z * Wreg[k].z + p.w * Wreg[k].w;
            }
            accB += __shfl_xor_sync(0xffffffffu, accB, 1);
            accB += __shfl_xor_sync(0xffffffffu, accB, 2);
            if (s == 0) sLP[h * LPITCH + jt + jj] = (accB + bph) * kScalePair;
        }
    }
    __syncthreads();
    // flush to g_lp[i][h][j], coalesced
    float* dst = g_lp + (size_t)i * H * NN;
    #pragma unroll
    for (int m = 0; m < 4; m++) {
        int idx = t + 256 * m;              // 0..1023 float4 slots
        int hh = idx >> 7, j4 = idx & 127;
        *(float4*)&dst[4 * idx] = *(const float4*)&sLP[hh * LPITCH + 4 * j4];
    }
}

// ---------------------------------------------------------------------------
// Kernel 5: attention core (NO pairwise access).
//   preload pair logits -> add scalar qk + point-dist logits -> softmax ->
//   write normalized weights to g_attn -> warp-per-row coalesced reductions
//   for res_scalar / res_point -> epilogue (R^T, norms).
// ---------------------------------------------------------------------------
__global__ __launch_bounds__(256) void attn_kernel(const float* __restrict__ rot,
                                                   const float* __restrict__ trans,
                                                   const float* __restrict__ point_weights)
{
    const int i = blockIdx.x;
    const int t = threadIdx.x;
    const int w = t >> 5, lane = t & 31;
    const int h = lane >> 2, s = lane & 3;

    __shared__ float sL[H * LPITCH];     // logits -> normalized weights
    __shared__ float sAccVp[192];

    // preload pair logits (coalesced)
    {
        const float* src = g_lp + (size_t)i * H * NN;
        #pragma unroll
        for (int m = 0; m < 4; m++) {
            int idx = t + 256 * m;
            int hh = idx >> 7, j4 = idx & 127;
            *(float4*)&sL[hh * LPITCH + 4 * j4] = *(const float4*)&src[4 * idx];
        }
    }
    const float4 qs4 = *(const float4*)&g_proj[i * PROJ_COLS + h * 16 + 4 * s];
    const float qp0 = g_qpg[i * 96 + h * 12 + 3 * s + 0];
    const float qp1 = g_qpg[i * 96 + h * 12 + 3 * s + 1];
    const float qp2 = g_qpg[i * 96 + h * 12 + 3 * s + 2];
    const float spw = log1pf(__expf(point_weights[h]));
    const float cP = -0.5f * spw * kScalePoint;
    __syncthreads();

    // scalar + point logits: warp w owns j in [64w, 64w+64)
    for (int u = 0; u < 64; u++) {
        int j = (w << 6) + u;
        const float4 ks4 = *(const float4*)&g_proj[j * PROJ_COLS + 128 + h * 16 + 4 * s];
        float accS = qs4.x * ks4.x + qs4.y * ks4.y + qs4.z * ks4.z + qs4.w * ks4.w;
        const float* kp = &g_kpg[j * 96 + h * 12 + 3 * s];
        float d0 = qp0 - kp[0], d1 = qp1 - kp[1], d2 = qp2 - kp[2];
        float part = accS * kScaleScalar + (d0 * d0 + d1 * d1 + d2 * d2) * cP;
        part += __shfl_xor_sync(0xffffffffu, part, 1);
        part += __shfl_xor_sync(0xffffffffu, part, 2);
        if (s == 0) sL[h * LPITCH + j] += part;
    }
    __syncthreads();

    // softmax: warp w owns head w; weights normalized in place
    {
        float* row = &sL[w * LPITCH];
        float m = -1e30f;
        for (int j = lane; j < NN; j += 32) m = fmaxf(m, row[j]);
        #pragma unroll
        for (int o = 16; o; o >>= 1) m = fmaxf(m, __shfl_xor_sync(0xffffffffu, m, o));
        float sum = 0.f;
        for (int j = lane; j < NN; j += 32) {
            float e = __expf(row[j] - m);
            row[j] = e;
            sum += e;
        }
        #pragma unroll
        for (int o = 16; o; o >>= 1) sum += __shfl_xor_sync(0xffffffffu, sum, o);
        float inv = 1.f / sum;
        for (int j = lane; j < NN; j += 32) row[j] *= inv;
    }
    __syncthreads();

    // write weights to g_attn (coalesced)
    {
        float* dst = g_attn + (size_t)i * H * NN;
        #pragma unroll
        for (int m = 0; m < 4; m++) {
            int idx = t + 256 * m;
            int hh = idx >> 7, j4 = idx & 127;
            *(float4*)&dst[4 * idx] = *(const float4*)&sL[hh * LPITCH + 4 * j4];
        }
    }

    float* resRow = g_res + (size_t)i * RES_COLS;

    // warp-per-row reductions: rows 0..127 = res_scalar, 128..319 = res_point
    for (int r = w; r < 320; r += 8) {
        const float* src;
        int hh;
        if (r < 128) { src = g_vsT + r * NN;        hh = r >> 4; }
        else         { src = g_vpT + (r - 128) * NN; hh = (r - 128) / 24; }
        const float* wrow = &sL[hh * LPITCH];
        float4 acc = make_float4(0.f, 0.f, 0.f, 0.f);
        #pragma unroll
        for (int it = 0; it < 4; it++) {
            int j0 = it * 128 + lane * 4;
            float4 v = *(const float4*)&src[j0];
            float4 g = *(const float4*)&wrow[j0];
            acc.x += g.x * v.x; acc.y += g.y * v.y;
            acc.z += g.z * v.z; acc.w += g.w * v.w;
        }
        float a = acc.x + acc.y + acc.z + acc.w;
        #pragma unroll
        for (int o = 16; o; o >>= 1) a += __shfl_xor_sync(0xffffffffu, a, o);
        if (lane == 0) {
            if (r < 128) resRow[r] = a;
            else         sAccVp[r - 128] = a;
        }
    }
    __syncthreads();

    // epilogue: back-transform points (R^T), norms
    if (t < 64) {
        int hh = t >> 3, d = t & 7;
        float t0 = trans[i * 3 + 0], t1 = trans[i * 3 + 1], t2 = trans[i * 3 + 2];
        float g0 = sAccVp[hh * 24 + d * 3 + 0] - t0;
        float g1 = sAccVp[hh * 24 + d * 3 + 1] - t1;
        float g2 = sAccVp[hh * 24 + d * 3 + 2] - t2;
        const float* R = rot + i * 9;
        float n2 = EPSV;
        #pragma unroll
        for (int r = 0; r < 3; r++) {
            float lr = g0 * R[r * 3 + 0] + g1 * R[r * 3 + 1] + g2 * R[r * 3 + 2];
            resRow[128 + hh * 24 + d * 3 + r] = lr;
            n2 += lr * lr;
        }
        resRow[320 + hh * 8 + d] = sqrtf(n2);
    }
}

// ---------------------------------------------------------------------------
// Kernel 6: res_pair.  resRow[384 + h*128 + d] = sum_j attn[i,h,j]*pair[i,j,d].
// Block per i; warp = head; lane = d4 (one float4 accumulator).
// ---------------------------------------------------------------------------
__global__ __launch_bounds__(256) void res_pair_kernel(const float* __restrict__ pairw)
{
    const int i = blockIdx.x;
    const int t = threadIdx.x;
    const int w = t >> 5, lane = t & 31;

    __shared__ float sW[H * NN];        // attn weights [h][j]
    __shared__ float sPair[32 * 132];   // 32-j tile, pitch 132

    {
        const float* src = g_attn + (size_t)i * H * NN;
        #pragma unroll
        for (int m = 0; m < 4; m++) {
            int idx = t + 256 * m;
            *(float4*)&sW[4 * idx] = *(const float4*)&src[4 * idx];
        }
    }
    const float* pairRow = pairw + (size_t)i * NN * PDIM;
    const float* wrow = &sW[w * NN];
    float4 acc = make_float4(0.f, 0.f, 0.f, 0.f);

    for (int jt = 0; jt < NN; jt += 32) {
        __syncthreads();
        #pragma unroll
        for (int m = 0; m < 4; m++) {
            int idx = t + 256 * m;
            int jj = idx >> 5, c4 = idx & 31;
            *(float4*)&sPair[jj * 132 + 4 * c4] =
                *(const float4*)&pairRow[(size_t)(jt + jj) * PDIM + 4 * c4];
        }
        __syncthreads();
        #pragma unroll 4
        for (int jj = 0; jj < 32; jj++) {
            float wg = wrow[jt + jj];
            float4 p = *(const float4*)&sPair[jj * 132 + 4 * lane];
            acc.x += wg * p.x; acc.y += wg * p.y;
            acc.z += wg * p.z; acc.w += wg * p.w;
        }
    }
    float* resRow = g_res + (size_t)i * RES_COLS;
    *((float4*)(resRow + 384 + w * 128) + lane) = acc;
}

// ---------------------------------------------------------------------------
extern "C" void kernel_launch(void* const* d_in, const int* in_sizes, int n_in,
                              void* d_out, int out_size)
{
    const float* x      = (const float*)d_in[0];
    const float* pairw  = (const float*)d_in[1];
    const float* rot    = (const float*)d_in[2];
    const float* trans  = (const float*)d_in[3];
    const float* Wsq    = (const float*)d_in[4];
    const float* Wsk    = (const float*)d_in[5];
    const float* Wsv    = (const float*)d_in[6];
    const float* Wpq    = (const float*)d_in[7];
    const float* Wpk    = (const float*)d_in[8];
    const float* Wpv    = (const float*)d_in[9];
    const float* pw     = (const float*)d_in[10];
    const float* Wpair  = (const float*)d_in[11];
    const float* bpair  = (const float*)d_in[12];
    const float* Wout   = (const float*)d_in[13];
    const float* bout   = (const float*)d_in[14];
    float* out = (float*)d_out;

    float *pWcat, *pProj, *pRes;
    cudaGetSymbolAddress((void**)&pWcat, g_Wcat);
    cudaGetSymbolAddress((void**)&pProj, g_proj);
    cudaGetSymbolAddress((void**)&pRes,  g_res);

    // 1. concat weights
    concat_w_kernel<<<(DIM * PROJ_COLS + 255) / 256, 256>>>(Wsq, Wsk, Wsv, Wpq, Wpk, Wpv);

    // 2. projections: proj[512,768] = x @ Wcat
    gemm64_kernel<<<dim3(PROJ_COLS / 64, NN / 64), 256>>>(x, pWcat, pProj, nullptr,
                                                          NN, PROJ_COLS, DIM);

    // 3. frame transform + transposed v layouts
    transform_kernel<<<131072 / 256, 256>>>(rot, trans);

    // 4. pair-bias logits (first pairwise stream)
    pair_logits_kernel<<<NN, 256>>>(pairw, Wpair, bpair);

    // 5. attention core (no pairwise)
    attn_kernel<<<NN, 256>>>(rot, trans, pw);

    // 6. res_pair (second pairwise stream)
    res_pair_kernel<<<NN, 256>>>(pairw);

    // 7. out = res[512,1408] @ Wout[1408,384] + bout
    gemm64_kernel<<<dim3(DIM / 64, NN / 64), 256>>>(pRes, Wout, out, bout,
                                                    NN, DIM, RES_COLS);
}

// round 9
// speedup vs baseline: 2.0184x; 1.2132x over previous
#include <cuda_runtime.h>
#include <cuda_bf16.h>
#include <cstdint>
#include <math.h>

// Problem constants
#define NN 512
#define DIM 384
#define PDIM 128
#define H 8
#define SK 16
#define SV 16
#define PK 4
#define PV 8
#define PROJ_COLS 768           // 128+128+128+96+96+192
#define RES_COLS 1408           // 128 + 192 + 64 + 1024
#define EPSV 1e-8f

__device__ __constant__ float kScaleScalar = 0.14433756729740643f;  // (3*16)^-0.5
__device__ __constant__ float kScalePoint  = 0.13608276348795434f;  // (3*4*4.5)^-0.5
__device__ __constant__ float kScalePair   = 0.57735026918962576f;  // 3^-0.5

// Scratch (allocation-free contract: __device__ globals)
__device__ float g_Wcat[DIM * PROJ_COLS];
__device__ float g_proj[NN * PROJ_COLS];
__device__ float g_QA[H * NN * 32];          // per-head q features [h][i][32]
__device__ float g_KB[H * NN * 32];          // per-head k features [h][j][32]
__device__ float g_vcombT[H * 40 * NN];      // per-head v (16 scalar + 24 point), [h][d][j]
__device__ float g_lp[NN * H * NN];          // logits [i][h][j]
__device__ float g_attn[NN * H * NN];        // normalized attn weights [i][h][j]
__device__ float g_res[NN * RES_COLS];

// ---------------------------------------------------------------------------
// cp.async helpers
// ---------------------------------------------------------------------------
__device__ __forceinline__ void cp_async16(void* smem_dst, const void* gmem_src) {
    uint32_t dst = (uint32_t)__cvta_generic_to_shared(smem_dst);
    asm volatile("cp.async.ca.shared.global [%0], [%1], 16;" :: "r"(dst), "l"(gmem_src));
}
__device__ __forceinline__ void cp_commit() {
    asm volatile("cp.async.commit_group;");
}
template <int N>
__device__ __forceinline__ void cp_wait() {
    asm volatile("cp.async.wait_group %0;" :: "n"(N));
}

// Stage a 32j x 128d pair tile (pitch 132 floats) with cp.async; 256 threads.
__device__ __forceinline__ void stage_pair_tile(float* sbuf, const float* pairRow,
                                                int jt, int t)
{
    #pragma unroll
    for (int m = 0; m < 4; m++) {
        int idx = t + 256 * m;           // 0..1023 float4 slots
        int jj = idx >> 5, c4 = idx & 31;
        cp_async16(&sbuf[jj * 132 + 4 * c4],
                   pairRow + (size_t)(jt + jj) * PDIM + 4 * c4);
    }
    cp_commit();
}

// ---------------------------------------------------------------------------
// Kernel 1: concat projection weights into [384 x 768]
// ---------------------------------------------------------------------------
__global__ void concat_w_kernel(const float* __restrict__ Wsq, const float* __restrict__ Wsk,
                                const float* __restrict__ Wsv, const float* __restrict__ Wpq,
                                const float* __restrict__ Wpk, const float* __restrict__ Wpv)
{
    int idx = blockIdx.x * blockDim.x + threadIdx.x;
    if (idx >= DIM * PROJ_COLS) return;
    int k = idx / PROJ_COLS;
    int c = idx - k * PROJ_COLS;
    float v;
    if (c < 128)       v = Wsq[k * 128 + c];
    else if (c < 256)  v = Wsk[k * 128 + (c - 128)];
    else if (c < 384)  v = Wsv[k * 128 + (c - 256)];
    else if (c < 480)  v = Wpq[k * 96 + (c - 384)];
    else if (c < 576)  v = Wpk[k * 96 + (c - 480)];
    else               v = Wpv[k * 192 + (c - 576)];
    g_Wcat[idx] = v;
}

// ---------------------------------------------------------------------------
// 64x64 tiled fp32 GEMM, 4x4 microtile, BK=16.  C (+)= A[M,K]*B[K,N].
// ---------------------------------------------------------------------------
__global__ __launch_bounds__(256) void gemm64_kernel(const float* __restrict__ A,
                                                     const float* __restrict__ B,
                                                     float* __restrict__ C,
                                                     int M, int N, int K,
                                                     int kChunk, int useAtomic)
{
    __shared__ float As[16][68];   // [k][m]
    __shared__ float Bs[16][68];   // [k][n]
    const int bm = blockIdx.y * 64;
    const int bn = blockIdx.x * 64;
    int k0 = blockIdx.z * kChunk;
    int k1 = k0 + kChunk; if (k1 > K) k1 = K;
    const int t  = threadIdx.x;
    const int tx = t & 15, ty = t >> 4;

    const int lm  = t >> 2;
    const int lk4 = (t & 3) * 4;
    const int lkb = t >> 4;
    const int lnb = (t & 15) * 4;

    float acc[4][4];
    #pragma unroll
    for (int r = 0; r < 4; r++)
        #pragma unroll
        for (int c = 0; c < 4; c++) acc[r][c] = 0.f;

    for (int kt = k0; kt < k1; kt += 16) {
        float4 a4 = *(const float4*)&A[(size_t)(bm + lm) * K + kt + lk4];
        float4 b4 = *(const float4*)&B[(size_t)(kt + lkb) * N + bn + lnb];
        __syncthreads();
        As[lk4 + 0][lm] = a4.x; As[lk4 + 1][lm] = a4.y;
        As[lk4 + 2][lm] = a4.z; As[lk4 + 3][lm] = a4.w;
        *(float4*)&Bs[lkb][lnb] = b4;
        __syncthreads();
        #pragma unroll
        for (int kk = 0; kk < 16; kk++) {
            float4 av = *(const float4*)&As[kk][ty * 4];
            float4 bv = *(const float4*)&Bs[kk][tx * 4];
            acc[0][0] += av.x * bv.x; acc[0][1] += av.x * bv.y; acc[0][2] += av.x * bv.z; acc[0][3] += av.x * bv.w;
            acc[1][0] += av.y * bv.x; acc[1][1] += av.y * bv.y; acc[1][2] += av.y * bv.z; acc[1][3] += av.y * bv.w;
            acc[2][0] += av.z * bv.x; acc[2][1] += av.z * bv.y; acc[2][2] += av.z * bv.z; acc[2][3] += av.z * bv.w;
            acc[3][0] += av.w * bv.x; acc[3][1] += av.w * bv.y; acc[3][2] += av.w * bv.z; acc[3][3] += av.w * bv.w;
        }
    }
    #pragma unroll
    for (int r = 0; r < 4; r++) {
        float* cp = &C[(size_t)(bm + ty * 4 + r) * N + bn + tx * 4];
        if (useAtomic) {
            atomicAdd(cp + 0, acc[r][0]); atomicAdd(cp + 1, acc[r][1]);
            atomicAdd(cp + 2, acc[r][2]); atomicAdd(cp + 3, acc[r][3]);
        } else {
            float4 v; v.x = acc[r][0]; v.y = acc[r][1]; v.z = acc[r][2]; v.w = acc[r][3];
            *(float4*)cp = v;
        }
    }
}

// ---------------------------------------------------------------------------
// Kernel 3: build per-head GEMM operand matrices.
//   QA[h][i][32] = [scaleS*q_s(16) | -2cP*qp_global(12) | cP*|qp|^2 | 1 | 0 0]
//   KB[h][j][32] = [k_s(16)        |  kp_global(12)     | 1 | cP*|kp|^2 | 0 0]
//   => QA.KB = scalar + point logits.
//   vcombT[h][d][j]: d<16 scalar v, d=16+3*pv+r global point v.
// ---------------------------------------------------------------------------
__global__ void transform_kernel(const float* __restrict__ rot, const float* __restrict__ trans,
                                 const float* __restrict__ point_weights)
{
    int tid = blockIdx.x * blockDim.x + threadIdx.x;
    if (tid >= H * NN) return;
    int h = tid >> 9, n = tid & 511;
    float pwh = log1pf(__expf(point_weights[h]));
    float cP = -0.5f * pwh * kScalePoint;
    const float* R = rot + n * 9;
    const float t0 = trans[n * 3 + 0], t1 = trans[n * 3 + 1], t2 = trans[n * 3 + 2];
    const float* pr = g_proj + (size_t)n * PROJ_COLS;
    float* qa = g_QA + ((size_t)h * NN + n) * 32;
    float* kb = g_KB + ((size_t)h * NN + n) * 32;

    #pragma unroll
    for (int d = 0; d < 16; d++) {
        qa[d] = pr[h * 16 + d] * kScaleScalar;
        kb[d] = pr[128 + h * 16 + d];
    }
    float qq = 0.f, kk = 0.f;
    #pragma unroll
    for (int pd = 0; pd < 4; pd++) {
        const float* q = pr + 384 + h * 12 + pd * 3;
        float g0 = q[0] * R[0] + q[1] * R[3] + q[2] * R[6] + t0;
        float g1 = q[0] * R[1] + q[1] * R[4] + q[2] * R[7] + t1;
        float g2 = q[0] * R[2] + q[1] * R[5] + q[2] * R[8] + t2;
        qa[16 + pd * 3 + 0] = -2.f * cP * g0;
        qa[16 + pd * 3 + 1] = -2.f * cP * g1;
        qa[16 + pd * 3 + 2] = -2.f * cP * g2;
        qq += g0 * g0 + g1 * g1 + g2 * g2;
        const float* k = pr + 480 + h * 12 + pd * 3;
        float f0 = k[0] * R[0] + k[1] * R[3] + k[2] * R[6] + t0;
        float f1 = k[0] * R[1] + k[1] * R[4] + k[2] * R[7] + t1;
        float f2 = k[0] * R[2] + k[1] * R[5] + k[2] * R[8] + t2;
        kb[16 + pd * 3 + 0] = f0;
        kb[16 + pd * 3 + 1] = f1;
        kb[16 + pd * 3 + 2] = f2;
        kk += f0 * f0 + f1 * f1 + f2 * f2;
    }
    qa[28] = cP * qq; qa[29] = 1.f; qa[30] = 0.f; qa[31] = 0.f;
    kb[28] = 1.f; kb[29] = cP * kk; kb[30] = 0.f; kb[31] = 0.f;

    #pragma unroll
    for (int d = 0; d < 16; d++)
        g_vcombT[((size_t)h * 40 + d) * NN + n] = pr[256 + h * 16 + d];
    #pragma unroll
    for (int pv = 0; pv < 8; pv++) {
        const float* v = pr + 576 + h * 24 + pv * 3;
        float g0 = v[0] * R[0] + v[1] * R[3] + v[2] * R[6] + t0;
        float g1 = v[0] * R[1] + v[1] * R[4] + v[2] * R[7] + t1;
        float g2 = v[0] * R[2] + v[1] * R[5] + v[2] * R[8] + t2;
        g_vcombT[((size_t)h * 40 + 16 + pv * 3 + 0) * NN + n] = g0;
        g_vcombT[((size_t)h * 40 + 16 + pv * 3 + 1) * NN + n] = g1;
        g_vcombT[((size_t)h * 40 + 16 + pv * 3 + 2) * NN + n] = g2;
    }
}

// ---------------------------------------------------------------------------
// Kernel 4: pair-bias logits, cp.async double-buffered.
//   g_lp[i][h][j] = (pair[i,j,:]@Wpair[:,h] + bpair[h]) * scalePair
// ---------------------------------------------------------------------------
__global__ __launch_bounds__(256) void pair_logits_kernel(const float* __restrict__ pairw,
                                                          const float* __restrict__ Wpair,
                                                          const float* __restrict__ bpair)
{
    const int i = blockIdx.x;
    const int t = threadIdx.x;
    const int w = t >> 5, lane = t & 31;
    const int h = lane >> 2, s = lane & 3;

    __shared__ __align__(16) float sP[2][32 * 132];

    float4 Wreg[8];
    #pragma unroll
    for (int k = 0; k < 8; k++) {
        int d0 = 16 * k + 4 * s;
        Wreg[k].x = Wpair[(d0 + 0) * 8 + h];
        Wreg[k].y = Wpair[(d0 + 1) * 8 + h];
        Wreg[k].z = Wpair[(d0 + 2) * 8 + h];
        Wreg[k].w = Wpair[(d0 + 3) * 8 + h];
    }
    const float bph = bpair[h];
    const float* pairRow = pairw + (size_t)i * NN * PDIM;

    stage_pair_tile(sP[0], pairRow, 0, t);
    for (int jt = 0; jt < NN; jt += 32) {
        int b = (jt >> 5) & 1;
        if (jt + 32 < NN) { stage_pair_tile(sP[b ^ 1], pairRow, jt + 32, t); cp_wait<1>(); }
        else              { cp_wait<0>(); }
        __syncthreads();
        #pragma unroll
        for (int u = 0; u < 4; u++) {
            int jj = (w << 2) + u;
            const float* prow = &sP[b][jj * 132 + 4 * s];
            float accB = 0.f;
            #pragma unroll
            for (int k = 0; k < 8; k++) {
                float4 p = *(const float4*)&prow[16 * k];
                accB += p.x * Wreg[k].x + p.y * Wreg[k].y
                      + p.z * Wreg[k].z + p.w * Wreg[k].w;
            }
            accB += __shfl_xor_sync(0xffffffffu, accB, 1);
            accB += __shfl_xor_sync(0xffffffffu, accB, 2);
            if (s == 0)
                g_lp[((size_t)i * H + h) * NN + jt + jj] = (accB + bph) * kScalePair;
        }
        __syncthreads();
    }
}

// ---------------------------------------------------------------------------
// Kernel 5: logit GEMM.  g_lp[i][h][j] += QA[h][i][:32] . KB[h][j][:32]
// Grid (8 jt, 8 it, 8 h); block computes 64i x 64j, K=32.
// ---------------------------------------------------------------------------
__global__ __launch_bounds__(256) void logit_gemm_kernel()
{
    const int h = blockIdx.z;
    const int i0 = blockIdx.y * 64;
    const int j0 = blockIdx.x * 64;
    __shared__ float sQ[32][68];   // [k][i]
    __shared__ float sK[32][68];   // [k][j]
    const int t = threadIdx.x, tx = t & 15, ty = t >> 4;

    #pragma unroll
    for (int m = 0; m < 8; m++) {
        int idx = t + 256 * m;
        int row = idx >> 5, k = idx & 31;
        sQ[k][row] = g_QA[((size_t)h * NN + i0 + row) * 32 + k];
        sK[k][row] = g_KB[((size_t)h * NN + j0 + row) * 32 + k];
    }
    __syncthreads();

    float acc[4][4];
    #pragma unroll
    for (int r = 0; r < 4; r++)
        #pragma unroll
        for (int c = 0; c < 4; c++) acc[r][c] = 0.f;

    #pragma unroll
    for (int kk = 0; kk < 32; kk++) {
        float4 a = *(const float4*)&sQ[kk][ty * 4];
        float4 b = *(const float4*)&sK[kk][tx * 4];
        acc[0][0] += a.x * b.x; acc[0][1] += a.x * b.y; acc[0][2] += a.x * b.z; acc[0][3] += a.x * b.w;
        acc[1][0] += a.y * b.x; acc[1][1] += a.y * b.y; acc[1][2] += a.y * b.z; acc[1][3] += a.y * b.w;
        acc[2][0] += a.z * b.x; acc[2][1] += a.z * b.y; acc[2][2] += a.z * b.z; acc[2][3] += a.z * b.w;
        acc[3][0] += a.w * b.x; acc[3][1] += a.w * b.y; acc[3][2] += a.w * b.z; acc[3][3] += a.w * b.w;
    }
    #pragma unroll
    for (int r = 0; r < 4; r++) {
        float4* p = (float4*)&g_lp[(((size_t)i0 + ty * 4 + r) * H + h) * NN + j0 + tx * 4];
        float4 v = *p;
        v.x += acc[r][0]; v.y += acc[r][1]; v.z += acc[r][2]; v.w += acc[r][3];
        *p = v;
    }
}

// ---------------------------------------------------------------------------
// Kernel 6: softmax.  Block per i, warp per head.  g_lp -> g_attn.
// ---------------------------------------------------------------------------
__global__ __launch_bounds__(256) void softmax_kernel()
{
    const int i = blockIdx.x;
    const int w = threadIdx.x >> 5, lane = threadIdx.x & 31;
    const float* src = g_lp + ((size_t)i * H + w) * NN;
    float* dst = g_attn + ((size_t)i * H + w) * NN;

    float4 v[4];
    #pragma unroll
    for (int q = 0; q < 4; q++) v[q] = *(const float4*)&src[q * 128 + lane * 4];

    float m = -1e30f;
    #pragma unroll
    for (int q = 0; q < 4; q++) {
        m = fmaxf(m, fmaxf(fmaxf(v[q].x, v[q].y), fmaxf(v[q].z, v[q].w)));
    }
    #pragma unroll
    for (int o = 16; o; o >>= 1) m = fmaxf(m, __shfl_xor_sync(0xffffffffu, m, o));

    float sum = 0.f;
    #pragma unroll
    for (int q = 0; q < 4; q++) {
        v[q].x = __expf(v[q].x - m); v[q].y = __expf(v[q].y - m);
        v[q].z = __expf(v[q].z - m); v[q].w = __expf(v[q].w - m);
        sum += v[q].x + v[q].y + v[q].z + v[q].w;
    }
    #pragma unroll
    for (int o = 16; o; o >>= 1) sum += __shfl_xor_sync(0xffffffffu, sum, o);
    float inv = 1.f / sum;
    #pragma unroll
    for (int q = 0; q < 4; q++) {
        v[q].x *= inv; v[q].y *= inv; v[q].z *= inv; v[q].w *= inv;
        *(float4*)&dst[q * 128 + lane * 4] = v[q];
    }
}

// ---------------------------------------------------------------------------
// Kernel 7: AV GEMM + epilogue.  Grid (8 it, 8 h); block: C[64 i][40 d], K=512.
// d<16 -> res_scalar; d in [16,40) -> global points, then R^T + norms.
// ---------------------------------------------------------------------------
__global__ __launch_bounds__(256) void av_kernel(const float* __restrict__ rot,
                                                 const float* __restrict__ trans)
{
    const int h = blockIdx.y;
    const int i0 = blockIdx.x * 64;
    const int t = threadIdx.x;
    const int ti = t >> 2, tg = t & 3;

    __shared__ float sA[64][33];
    __shared__ float sV[40][33];
    __shared__ float sC[64][41];

    float acc[10];
    #pragma unroll
    for (int q = 0; q < 10; q++) acc[q] = 0.f;

    for (int jt = 0; jt < NN; jt += 32) {
        __syncthreads();
        #pragma unroll
        for (int m = 0; m < 8; m++) {
            int idx = t + 256 * m;
            int il = idx >> 5, jj = idx & 31;
            sA[il][jj] = g_attn[(((size_t)i0 + il) * H + h) * NN + jt + jj];
        }
        #pragma unroll
        for (int m = 0; m < 5; m++) {
            int idx = t + 256 * m;
            int d = idx >> 5, jj = idx & 31;
            sV[d][jj] = g_vcombT[((size_t)h * 40 + d) * NN + jt + jj];
        }
        __syncthreads();
        #pragma unroll 4
        for (int jj = 0; jj < 32; jj++) {
            float a = sA[ti][jj];
            #pragma unroll
            for (int q = 0; q < 10; q++) acc[q] += a * sV[tg * 10 + q][jj];
        }
    }
    __syncthreads();
    #pragma unroll
    for (int q = 0; q < 10; q++) sC[ti][tg * 10 + q] = acc[q];
    __syncthreads();

    // scalar outputs
    #pragma unroll
    for (int m = 0; m < 4; m++) {
        int idx = t + 256 * m;
        int il = idx >> 4, d = idx & 15;
        g_res[((size_t)i0 + il) * RES_COLS + h * 16 + d] = sC[il][d];
    }
    // point outputs: back-transform + norm
    #pragma unroll
    for (int m = 0; m < 2; m++) {
        int idx = t + 256 * m;
        int il = idx >> 3, pv = idx & 7;
        int i = i0 + il;
        float g0 = sC[il][16 + pv * 3 + 0] - trans[i * 3 + 0];
        float g1 = sC[il][16 + pv * 3 + 1] - trans[i * 3 + 1];
        float g2 = sC[il][16 + pv * 3 + 2] - trans[i * 3 + 2];
        const float* R = rot + i * 9;
        float n2 = EPSV;
        #pragma unroll
        for (int r = 0; r < 3; r++) {
            float lr = g0 * R[r * 3 + 0] + g1 * R[r * 3 + 1] + g2 * R[r * 3 + 2];
            g_res[(size_t)i * RES_COLS + 128 + h * 24 + pv * 3 + r] = lr;
            n2 += lr * lr;
        }
        g_res[(size_t)i * RES_COLS + 320 + h * 8 + pv] = sqrtf(n2);
    }
}

// ---------------------------------------------------------------------------
// Kernel 8: res_pair, cp.async double-buffered.
//   g_res[i][384 + h*128 + d] = sum_j attn[i,h,j] * pair[i,j,d]
// Warp = head, lane = d4 (float4 accumulator).
// ---------------------------------------------------------------------------
__global__ __launch_bounds__(256) void res_pair_kernel(const float* __restrict__ pairw)
{
    const int i = blockIdx.x;
    const int t = threadIdx.x;
    const int w = t >> 5, lane = t & 31;

    __shared__ __align__(16) float sP[2][32 * 132];
    __shared__ float sW[H * NN];

    {
        const float* src = g_attn + (size_t)i * H * NN;
        #pragma unroll
        for (int m = 0; m < 4; m++) {
            int idx = t + 256 * m;
            *(float4*)&sW[4 * idx] = *(const float4*)&src[4 * idx];
        }
    }
    const float* pairRow = pairw + (size_t)i * NN * PDIM;
    float4 acc = make_float4(0.f, 0.f, 0.f, 0.f);

    stage_pair_tile(sP[0], pairRow, 0, t);
    for (int jt = 0; jt < NN; jt += 32) {
        int b = (jt >> 5) & 1;
        if (jt + 32 < NN) { stage_pair_tile(sP[b ^ 1], pairRow, jt + 32, t); cp_wait<1>(); }
        else              { cp_wait<0>(); }
        __syncthreads();
        const float* wrow = &sW[w * NN + jt];
        #pragma unroll 4
        for (int jj = 0; jj < 32; jj++) {
            float wg = wrow[jj];
            float4 p = *(const float4*)&sP[b][jj * 132 + 4 * lane];
            acc.x += wg * p.x; acc.y += wg * p.y;
            acc.z += wg * p.z; acc.w += wg * p.w;
        }
        __syncthreads();
    }

    *(float4*)&g_res[(size_t)i * RES_COLS + 384 + w * 128 + 4 * lane] = acc;
}

// ---------------------------------------------------------------------------
// Kernel 9: init output with bias (for split-K atomic GEMM)
// ---------------------------------------------------------------------------
__global__ void init_out_kernel(float* __restrict__ out, const float* __restrict__ bout)
{
    int idx = blockIdx.x * blockDim.x + threadIdx.x;
    if (idx < NN * DIM) out[idx] = bout[idx % DIM];
}

// ---------------------------------------------------------------------------
extern "C" void kernel_launch(void* const* d_in, const int* in_sizes, int n_in,
                              void* d_out, int out_size)
{
    const float* x      = (const float*)d_in[0];
    const float* pairw  = (const float*)d_in[1];
    const float* rot    = (const float*)d_in[2];
    const float* trans  = (const float*)d_in[3];
    const float* Wsq    = (const float*)d_in[4];
    const float* Wsk    = (const float*)d_in[5];
    const float* Wsv    = (const float*)d_in[6];
    const float* Wpq    = (const float*)d_in[7];
    const float* Wpk    = (const float*)d_in[8];
    const float* Wpv    = (const float*)d_in[9];
    const float* pw     = (const float*)d_in[10];
    const float* Wpair  = (const float*)d_in[11];
    const float* bpair  = (const float*)d_in[12];
    const float* Wout   = (const float*)d_in[13];
    const float* bout   = (const float*)d_in[14];
    float* out = (float*)d_out;

    float *pWcat, *pProj, *pRes;
    cudaGetSymbolAddress((void**)&pWcat, g_Wcat);
    cudaGetSymbolAddress((void**)&pProj, g_proj);
    cudaGetSymbolAddress((void**)&pRes,  g_res);

    // 1. concat weights
    concat_w_kernel<<<(DIM * PROJ_COLS + 255) / 256, 256>>>(Wsq, Wsk, Wsv, Wpq, Wpk, Wpv);

    // 2. projections: proj[512,768] = x @ Wcat
    gemm64_kernel<<<dim3(PROJ_COLS / 64, NN / 64), 256>>>(x, pWcat, pProj,
                                                          NN, PROJ_COLS, DIM, DIM, 0);

    // 3. build QA/KB/vcombT
    transform_kernel<<<(H * NN) / 256, 256>>>(rot, trans, pw);

    // 4. pair-bias logits (first pairwise stream, async pipelined)
    pair_logits_kernel<<<NN, 256>>>(pairw, Wpair, bpair);

    // 5. scalar + point logits via K=32 GEMM
    logit_gemm_kernel<<<dim3(8, 8, 8), 256>>>();

    // 6. softmax
    softmax_kernel<<<NN, 256>>>();

    // 7. AV GEMM (res_scalar + res_point + norms)
    av_kernel<<<dim3(8, 8), 256>>>(rot, trans);

    // 8. res_pair (second pairwise stream, async pipelined)
    res_pair_kernel<<<NN, 256>>>(pairw);

    // 9-10. out = res @ Wout + bout   (split-K=4, atomic)
    init_out_kernel<<<(NN * DIM + 255) / 256, 256>>>(out, bout);
    gemm64_kernel<<<dim3(DIM / 64, NN / 64, 4), 256>>>(pRes, Wout, out,
                                                       NN, DIM, RES_COLS, 352, 1);
}

// round 10
// speedup vs baseline: 2.3681x; 1.1732x over previous
#include <cuda_runtime.h>
#include <cuda_bf16.h>
#include <cstdint>
#include <math.h>

// Problem constants
#define NN 512
#define DIM 384
#define PDIM 128
#define H 8
#define SK 16
#define SV 16
#define PK 4
#define PV 8
#define PROJ_COLS 768           // 128+128+128+96+96+192
#define RES_COLS 1408           // 128 + 192 + 64 + 1024
#define EPSV 1e-8f
#define LP 516                  // sL pitch (floats): 16B aligned, bank step 4

__device__ __constant__ float kScaleScalar = 0.14433756729740643f;  // (3*16)^-0.5
__device__ __constant__ float kScalePoint  = 0.13608276348795434f;  // (3*4*4.5)^-0.5
__device__ __constant__ float kScalePair   = 0.57735026918962576f;  // 3^-0.5

// Scratch (allocation-free contract: __device__ globals)
__device__ float g_Wcat[DIM * PROJ_COLS];
__device__ float g_proj[NN * PROJ_COLS];
__device__ float g_QA[H * NN * 32];          // per-head q features [h][i][32]
__device__ float g_KB[H * NN * 32];          // per-head k features [h][j][32]
__device__ float g_vcombT[H * 40 * NN];      // per-head v (16 scalar + 24 point), [h][d][j]
__device__ float g_lp[NN * H * NN];          // QK logits [i][h][j]
__device__ float g_attn[NN * H * NN];        // normalized attn weights [i][h][j]
__device__ float g_res[NN * RES_COLS];

// ---------------------------------------------------------------------------
// cp.async helpers (.cg = L2-only, data is touch-once)
// ---------------------------------------------------------------------------
__device__ __forceinline__ void cp_async16(void* smem_dst, const void* gmem_src) {
    uint32_t dst = (uint32_t)__cvta_generic_to_shared(smem_dst);
    asm volatile("cp.async.cg.shared.global [%0], [%1], 16;" :: "r"(dst), "l"(gmem_src));
}
__device__ __forceinline__ void cp_commit() {
    asm volatile("cp.async.commit_group;");
}
template <int N>
__device__ __forceinline__ void cp_wait() {
    asm volatile("cp.async.wait_group %0;" :: "n"(N));
}

// Stage one contiguous 32j x 128d pair tile (16 KB) with cp.async; 256 threads.
__device__ __forceinline__ void stage_pair_tile(float* sbuf, const float* pairRow,
                                                int jt, int t)
{
    const float* src = pairRow + (size_t)jt * PDIM;
    #pragma unroll
    for (int m = 0; m < 4; m++) {
        int idx = t + 256 * m;           // 0..1023 float4 slots
        cp_async16(&sbuf[4 * idx], src + 4 * idx);
    }
    cp_commit();
}

// ---------------------------------------------------------------------------
// Kernel 1: concat projection weights into [384 x 768]
// ---------------------------------------------------------------------------
__global__ void concat_w_kernel(const float* __restrict__ Wsq, const float* __restrict__ Wsk,
                                const float* __restrict__ Wsv, const float* __restrict__ Wpq,
                                const float* __restrict__ Wpk, const float* __restrict__ Wpv)
{
    int idx = blockIdx.x * blockDim.x + threadIdx.x;
    if (idx >= DIM * PROJ_COLS) return;
    int k = idx / PROJ_COLS;
    int c = idx - k * PROJ_COLS;
    float v;
    if (c < 128)       v = Wsq[k * 128 + c];
    else if (c < 256)  v = Wsk[k * 128 + (c - 128)];
    else if (c < 384)  v = Wsv[k * 128 + (c - 256)];
    else if (c < 480)  v = Wpq[k * 96 + (c - 384)];
    else if (c < 576)  v = Wpk[k * 96 + (c - 480)];
    else               v = Wpv[k * 192 + (c - 576)];
    g_Wcat[idx] = v;
}

// ---------------------------------------------------------------------------
// 64x64 tiled fp32 GEMM, 4x4 microtile, BK=16.  C (+)= A[M,K]*B[K,N].
// ---------------------------------------------------------------------------
__global__ __launch_bounds__(256) void gemm64_kernel(const float* __restrict__ A,
                                                     const float* __restrict__ B,
                                                     float* __restrict__ C,
                                                     int M, int N, int K,
                                                     int kChunk, int useAtomic)
{
    __shared__ float As[16][68];   // [k][m]
    __shared__ float Bs[16][68];   // [k][n]
    const int bm = blockIdx.y * 64;
    const int bn = blockIdx.x * 64;
    int k0 = blockIdx.z * kChunk;
    int k1 = k0 + kChunk; if (k1 > K) k1 = K;
    const int t  = threadIdx.x;
    const int tx = t & 15, ty = t >> 4;

    const int lm  = t >> 2;
    const int lk4 = (t & 3) * 4;
    const int lkb = t >> 4;
    const int lnb = (t & 15) * 4;

    float acc[4][4];
    #pragma unroll
    for (int r = 0; r < 4; r++)
        #pragma unroll
        for (int c = 0; c < 4; c++) acc[r][c] = 0.f;

    for (int kt = k0; kt < k1; kt += 16) {
        float4 a4 = *(const float4*)&A[(size_t)(bm + lm) * K + kt + lk4];
        float4 b4 = *(const float4*)&B[(size_t)(kt + lkb) * N + bn + lnb];
        __syncthreads();
        As[lk4 + 0][lm] = a4.x; As[lk4 + 1][lm] = a4.y;
        As[lk4 + 2][lm] = a4.z; As[lk4 + 3][lm] = a4.w;
        *(float4*)&Bs[lkb][lnb] = b4;
        __syncthreads();
        #pragma unroll
        for (int kk = 0; kk < 16; kk++) {
            float4 av = *(const float4*)&As[kk][ty * 4];
            float4 bv = *(const float4*)&Bs[kk][tx * 4];
            acc[0][0] += av.x * bv.x; acc[0][1] += av.x * bv.y; acc[0][2] += av.x * bv.z; acc[0][3] += av.x * bv.w;
            acc[1][0] += av.y * bv.x; acc[1][1] += av.y * bv.y; acc[1][2] += av.y * bv.z; acc[1][3] += av.y * bv.w;
            acc[2][0] += av.z * bv.x; acc[2][1] += av.z * bv.y; acc[2][2] += av.z * bv.z; acc[2][3] += av.z * bv.w;
            acc[3][0] += av.w * bv.x; acc[3][1] += av.w * bv.y; acc[3][2] += av.w * bv.z; acc[3][3] += av.w * bv.w;
        }
    }
    #pragma unroll
    for (int r = 0; r < 4; r++) {
        float* cp = &C[(size_t)(bm + ty * 4 + r) * N + bn + tx * 4];
        if (useAtomic) {
            atomicAdd(cp + 0, acc[r][0]); atomicAdd(cp + 1, acc[r][1]);
            atomicAdd(cp + 2, acc[r][2]); atomicAdd(cp + 3, acc[r][3]);
        } else {
            float4 v; v.x = acc[r][0]; v.y = acc[r][1]; v.z = acc[r][2]; v.w = acc[r][3];
            *(float4*)cp = v;
        }
    }
}

// ---------------------------------------------------------------------------
// Kernel 3: build per-head GEMM operand matrices.
// ---------------------------------------------------------------------------
__global__ void transform_kernel(const float* __restrict__ rot, const float* __restrict__ trans,
                                 const float* __restrict__ point_weights)
{
    int tid = blockIdx.x * blockDim.x + threadIdx.x;
    if (tid >= H * NN) return;
    int h = tid >> 9, n = tid & 511;
    float pwh = log1pf(__expf(point_weights[h]));
    float cP = -0.5f * pwh * kScalePoint;
    const float* R = rot + n * 9;
    const float t0 = trans[n * 3 + 0], t1 = trans[n * 3 + 1], t2 = trans[n * 3 + 2];
    const float* pr = g_proj + (size_t)n * PROJ_COLS;
    float* qa = g_QA + ((size_t)h * NN + n) * 32;
    float* kb = g_KB + ((size_t)h * NN + n) * 32;

    #pragma unroll
    for (int d = 0; d < 16; d++) {
        qa[d] = pr[h * 16 + d] * kScaleScalar;
        kb[d] = pr[128 + h * 16 + d];
    }
    float qq = 0.f, kk = 0.f;
    #pragma unroll
    for (int pd = 0; pd < 4; pd++) {
        const float* q = pr + 384 + h * 12 + pd * 3;
        float g0 = q[0] * R[0] + q[1] * R[3] + q[2] * R[6] + t0;
        float g1 = q[0] * R[1] + q[1] * R[4] + q[2] * R[7] + t1;
        float g2 = q[0] * R[2] + q[1] * R[5] + q[2] * R[8] + t2;
        qa[16 + pd * 3 + 0] = -2.f * cP * g0;
        qa[16 + pd * 3 + 1] = -2.f * cP * g1;
        qa[16 + pd * 3 + 2] = -2.f * cP * g2;
        qq += g0 * g0 + g1 * g1 + g2 * g2;
        const float* k = pr + 480 + h * 12 + pd * 3;
        float f0 = k[0] * R[0] + k[1] * R[3] + k[2] * R[6] + t0;
        float f1 = k[0] * R[1] + k[1] * R[4] + k[2] * R[7] + t1;
        float f2 = k[0] * R[2] + k[1] * R[5] + k[2] * R[8] + t2;
        kb[16 + pd * 3 + 0] = f0;
        kb[16 + pd * 3 + 1] = f1;
        kb[16 + pd * 3 + 2] = f2;
        kk += f0 * f0 + f1 * f1 + f2 * f2;
    }
    qa[28] = cP * qq; qa[29] = 1.f; qa[30] = 0.f; qa[31] = 0.f;
    kb[28] = 1.f; kb[29] = cP * kk; kb[30] = 0.f; kb[31] = 0.f;

    #pragma unroll
    for (int d = 0; d < 16; d++)
        g_vcombT[((size_t)h * 40 + d) * NN + n] = pr[256 + h * 16 + d];
    #pragma unroll
    for (int pv = 0; pv < 8; pv++) {
        const float* v = pr + 576 + h * 24 + pv * 3;
        float g0 = v[0] * R[0] + v[1] * R[3] + v[2] * R[6] + t0;
        float g1 = v[0] * R[1] + v[1] * R[4] + v[2] * R[7] + t1;
        float g2 = v[0] * R[2] + v[1] * R[5] + v[2] * R[8] + t2;
        g_vcombT[((size_t)h * 40 + 16 + pv * 3 + 0) * NN + n] = g0;
        g_vcombT[((size_t)h * 40 + 16 + pv * 3 + 1) * NN + n] = g1;
        g_vcombT[((size_t)h * 40 + 16 + pv * 3 + 2) * NN + n] = g2;
    }
}

// ---------------------------------------------------------------------------
// Kernel 4: QK logit GEMM (runs FIRST).  g_lp[i][h][j] = QA[h][i] . KB[h][j]
// Grid (8 jt, 8 it, 8 h); block computes 64i x 64j, K=32.
// ---------------------------------------------------------------------------
__global__ __launch_bounds__(256) void logit_gemm_kernel()
{
    const int h = blockIdx.z;
    const int i0 = blockIdx.y * 64;
    const int j0 = blockIdx.x * 64;
    __shared__ float sQ[32][68];   // [k][i]
    __shared__ float sK[32][68];   // [k][j]
    const int t = threadIdx.x, tx = t & 15, ty = t >> 4;

    #pragma unroll
    for (int m = 0; m < 8; m++) {
        int idx = t + 256 * m;
        int row = idx >> 5, k = idx & 31;
        sQ[k][row] = g_QA[((size_t)h * NN + i0 + row) * 32 + k];
        sK[k][row] = g_KB[((size_t)h * NN + j0 + row) * 32 + k];
    }
    __syncthreads();

    float acc[4][4];
    #pragma unroll
    for (int r = 0; r < 4; r++)
        #pragma unroll
        for (int c = 0; c < 4; c++) acc[r][c] = 0.f;

    #pragma unroll
    for (int kk = 0; kk < 32; kk++) {
        float4 a = *(const float4*)&sQ[kk][ty * 4];
        float4 b = *(const float4*)&sK[kk][tx * 4];
        acc[0][0] += a.x * b.x; acc[0][1] += a.x * b.y; acc[0][2] += a.x * b.z; acc[0][3] += a.x * b.w;
        acc[1][0] += a.y * b.x; acc[1][1] += a.y * b.y; acc[1][2] += a.y * b.z; acc[1][3] += a.y * b.w;
        acc[2][0] += a.z * b.x; acc[2][1] += a.z * b.y; acc[2][2] += a.z * b.z; acc[2][3] += a.z * b.w;
        acc[3][0] += a.w * b.x; acc[3][1] += a.w * b.y; acc[3][2] += a.w * b.z; acc[3][3] += a.w * b.w;
    }
    #pragma unroll
    for (int r = 0; r < 4; r++) {
        float4 v;
        v.x = acc[r][0]; v.y = acc[r][1]; v.z = acc[r][2]; v.w = acc[r][3];
        *(float4*)&g_lp[(((size_t)i0 + ty * 4 + r) * H + h) * NN + j0 + tx * 4] = v;
    }
}

// ---------------------------------------------------------------------------
// Kernel 5: pair-bias logits + softmax (fused).  Block per i.
//   preload QK logits -> stream pairwise (cp.async.cg double-buffer),
//   head-paired lanes (lane = hp*8+s): 4 LDS.128 + 32 FFMA per row ->
//   softmax per head -> write g_attn.
// ---------------------------------------------------------------------------
__global__ __launch_bounds__(256) void pair_logits_sm_kernel(const float* __restrict__ pairw,
                                                             const float* __restrict__ Wpair,
                                                             const float* __restrict__ bpair)
{
    const int i = blockIdx.x;
    const int t = threadIdx.x;
    const int w = t >> 5, lane = t & 31;
    const int hp = lane >> 3;            // head pair 0..3 -> heads 2hp, 2hp+1
    const int s  = lane & 7;             // d-slice 0..7

    __shared__ __align__(16) float sP[2][32 * 128];   // 2 x 16 KB tiles
    __shared__ float sL[H * LP];                      // logits -> weights

    const int h0 = 2 * hp, h1 = 2 * hp + 1;
    float4 W0[4], W1[4];
    #pragma unroll
    for (int k = 0; k < 4; k++) {
        int d0 = 4 * (s + 8 * k);
        W0[k].x = Wpair[(d0 + 0) * 8 + h0]; W1[k].x = Wpair[(d0 + 0) * 8 + h1];
        W0[k].y = Wpair[(d0 + 1) * 8 + h0]; W1[k].y = Wpair[(d0 + 1) * 8 + h1];
        W0[k].z = Wpair[(d0 + 2) * 8 + h0]; W1[k].z = Wpair[(d0 + 2) * 8 + h1];
        W0[k].w = Wpair[(d0 + 3) * 8 + h0]; W1[k].w = Wpair[(d0 + 3) * 8 + h1];
    }
    const float bb0 = bpair[h0] * kScalePair;
    const float bb1 = bpair[h1] * kScalePair;
    const float* pairRow = pairw + (size_t)i * NN * PDIM;

    // preload QK logits into sL
    {
        const float* src = g_lp + (size_t)i * H * NN;
        #pragma unroll
        for (int m = 0; m < 4; m++) {
            int idx = t + 256 * m;
            int hh = idx >> 7, j4 = idx & 127;
            *(float4*)&sL[hh * LP + 4 * j4] = *(const float4*)&src[4 * idx];
        }
    }

    stage_pair_tile(sP[0], pairRow, 0, t);
    __syncthreads();                       // sL preload visible before +=
    for (int jt = 0; jt < NN; jt += 32) {
        int b = (jt >> 5) & 1;
        if (jt + 32 < NN) { stage_pair_tile(sP[b ^ 1], pairRow, jt + 32, t); cp_wait<1>(); }
        else              { cp_wait<0>(); }
        __syncthreads();
        #pragma unroll
        for (int u = 0; u < 4; u++) {
            int jj = (w << 2) + u;
            const float* row = &sP[b][jj * 128];
            float a0 = 0.f, a1 = 0.f;
            #pragma unroll
            for (int k = 0; k < 4; k++) {
                float4 p = *(const float4*)&row[4 * (s + 8 * k)];
                a0 += p.x * W0[k].x + p.y * W0[k].y + p.z * W0[k].z + p.w * W0[k].w;
                a1 += p.x * W1[k].x + p.y * W1[k].y + p.z * W1[k].z + p.w * W1[k].w;
            }
            #pragma unroll
            for (int o = 1; o < 8; o <<= 1) {
                a0 += __shfl_xor_sync(0xffffffffu, a0, o);
                a1 += __shfl_xor_sync(0xffffffffu, a1, o);
            }
            if (s == 0) {
                int j = jt + jj;
                sL[h0 * LP + j] += a0 * kScalePair + bb0;
                sL[h1 * LP + j] += a1 * kScalePair + bb1;
            }
        }
        __syncthreads();
    }

    // softmax: warp w owns head w
    {
        float* row = &sL[w * LP];
        float m = -1e30f;
        for (int j = lane; j < NN; j += 32) m = fmaxf(m, row[j]);
        #pragma unroll
        for (int o = 16; o; o >>= 1) m = fmaxf(m, __shfl_xor_sync(0xffffffffu, m, o));
        float sum = 0.f;
        for (int j = lane; j < NN; j += 32) {
            float e = __expf(row[j] - m);
            row[j] = e;
            sum += e;
        }
        #pragma unroll
        for (int o = 16; o; o >>= 1) sum += __shfl_xor_sync(0xffffffffu, sum, o);
        float inv = 1.f / sum;
        for (int j = lane; j < NN; j += 32) row[j] *= inv;
    }
    __syncthreads();

    // write weights to g_attn (coalesced)
    {
        float* dst = g_attn + (size_t)i * H * NN;
        #pragma unroll
        for (int m = 0; m < 4; m++) {
            int idx = t + 256 * m;
            int hh = idx >> 7, j4 = idx & 127;
            *(float4*)&dst[4 * idx] = *(const float4*)&sL[hh * LP + 4 * j4];
        }
    }
}

// ---------------------------------------------------------------------------
// Kernel 6: AV GEMM + epilogue.  Grid (8 it, 8 h); block: C[64 i][40 d], K=512.
// ---------------------------------------------------------------------------
__global__ __launch_bounds__(256) void av_kernel(const float* __restrict__ rot,
                                                 const float* __restrict__ trans)
{
    const int h = blockIdx.y;
    const int i0 = blockIdx.x * 64;
    const int t = threadIdx.x;
    const int ti = t >> 2, tg = t & 3;

    __shared__ float sA[64][33];
    __shared__ float sV[40][33];
    __shared__ float sC[64][41];

    float acc[10];
    #pragma unroll
    for (int q = 0; q < 10; q++) acc[q] = 0.f;

    for (int jt = 0; jt < NN; jt += 32) {
        __syncthreads();
        #pragma unroll
        for (int m = 0; m < 8; m++) {
            int idx = t + 256 * m;
            int il = idx >> 5, jj = idx & 31;
            sA[il][jj] = g_attn[(((size_t)i0 + il) * H + h) * NN + jt + jj];
        }
        #pragma unroll
        for (int m = 0; m < 5; m++) {
            int idx = t + 256 * m;
            int d = idx >> 5, jj = idx & 31;
            sV[d][jj] = g_vcombT[((size_t)h * 40 + d) * NN + jt + jj];
        }
        __syncthreads();
        #pragma unroll 4
        for (int jj = 0; jj < 32; jj++) {
            float a = sA[ti][jj];
            #pragma unroll
            for (int q = 0; q < 10; q++) acc[q] += a * sV[tg * 10 + q][jj];
        }
    }
    __syncthreads();
    #pragma unroll
    for (int q = 0; q < 10; q++) sC[ti][tg * 10 + q] = acc[q];
    __syncthreads();

    #pragma unroll
    for (int m = 0; m < 4; m++) {
        int idx = t + 256 * m;
        int il = idx >> 4, d = idx & 15;
        g_res[((size_t)i0 + il) * RES_COLS + h * 16 + d] = sC[il][d];
    }
    #pragma unroll
    for (int m = 0; m < 2; m++) {
        int idx = t + 256 * m;
        int il = idx >> 3, pv = idx & 7;
        int i = i0 + il;
        float g0 = sC[il][16 + pv * 3 + 0] - trans[i * 3 + 0];
        float g1 = sC[il][16 + pv * 3 + 1] - trans[i * 3 + 1];
        float g2 = sC[il][16 + pv * 3 + 2] - trans[i * 3 + 2];
        const float* R = rot + i * 9;
        float n2 = EPSV;
        #pragma unroll
        for (int r = 0; r < 3; r++) {
            float lr = g0 * R[r * 3 + 0] + g1 * R[r * 3 + 1] + g2 * R[r * 3 + 2];
            g_res[(size_t)i * RES_COLS + 128 + h * 24 + pv * 3 + r] = lr;
            n2 += lr * lr;
        }
        g_res[(size_t)i * RES_COLS + 320 + h * 8 + pv] = sqrtf(n2);
    }
}

// ---------------------------------------------------------------------------
// Kernel 7: res_pair.  Warp = (head-group hg = w&1 -> 4 heads, row-eighth
// jh = w>>1).  Each pair row read by only 4 warps (was 8).  Partials
// combined through SMEM at block end.
// ---------------------------------------------------------------------------
__global__ __launch_bounds__(256) void res_pair_kernel(const float* __restrict__ pairw)
{
    const int i = blockIdx.x;
    const int t = threadIdx.x;
    const int w = t >> 5, lane = t & 31;
    const int hg = w & 1;                 // heads 4hg .. 4hg+3
    const int jh = w >> 1;                // rows [8jh, 8jh+8) within tile

    __shared__ __align__(16) float sP[2][32 * 128];   // 32 KB
    __shared__ float sW[H * NN];                      // attn [h][j], 16 KB
    __shared__ float4 sPart[8][4][32];                // 16 KB partials

    {
        const float* src = g_attn + (size_t)i * H * NN;
        #pragma unroll
        for (int m = 0; m < 4; m++) {
            int idx = t + 256 * m;
            *(float4*)&sW[4 * idx] = *(const float4*)&src[4 * idx];
        }
    }
    const float* pairRow = pairw + (size_t)i * NN * PDIM;
    const float* w0 = &sW[(4 * hg + 0) * NN];
    const float* w1 = &sW[(4 * hg + 1) * NN];
    const float* w2 = &sW[(4 * hg + 2) * NN];
    const float* w3 = &sW[(4 * hg + 3) * NN];

    float4 acc0 = make_float4(0.f, 0.f, 0.f, 0.f);
    float4 acc1 = acc0, acc2 = acc0, acc3 = acc0;

    stage_pair_tile(sP[0], pairRow, 0, t);
    for (int jt = 0; jt < NN; jt += 32) {
        int b = (jt >> 5) & 1;
        if (jt + 32 < NN) { stage_pair_tile(sP[b ^ 1], pairRow, jt + 32, t); cp_wait<1>(); }
        else              { cp_wait<0>(); }
        __syncthreads();
        const float* base = &sP[b][(8 * jh) * 128 + 4 * lane];
        #pragma unroll
        for (int r = 0; r < 8; r++) {
            int j = jt + 8 * jh + r;
            float4 p = *(const float4*)&base[r * 128];
            float g0 = w0[j], g1 = w1[j], g2 = w2[j], g3 = w3[j];
            acc0.x += g0 * p.x; acc0.y += g0 * p.y; acc0.z += g0 * p.z; acc0.w += g0 * p.w;
            acc1.x += g1 * p.x; acc1.y += g1 * p.y; acc1.z += g1 * p.z; acc1.w += g1 * p.w;
            acc2.x += g2 * p.x; acc2.y += g2 * p.y; acc2.z += g2 * p.z; acc2.w += g2 * p.w;
            acc3.x += g3 * p.x; acc3.y += g3 * p.y; acc3.z += g3 * p.z; acc3.w += g3 * p.w;
        }
        __syncthreads();
    }

    sPart[w][0][lane] = acc0;
    sPart[w][1][lane] = acc1;
    sPart[w][2][lane] = acc2;
    sPart[w][3][lane] = acc3;
    __syncthreads();

    // thread t = h*32 + d4: sum 4 row-eighth partials
    {
        int h = t >> 5, d4 = t & 31;
        int hgq = h >> 2, hh = h & 3;
        float4 r = make_float4(0.f, 0.f, 0.f, 0.f);
        #pragma unroll
        for (int q = 0; q < 4; q++) {
            float4 p = sPart[2 * q + hgq][hh][d4];
            r.x += p.x; r.y += p.y; r.z += p.z; r.w += p.w;
        }
        *(float4*)&g_res[(size_t)i * RES_COLS + 384 + h * 128 + 4 * d4] = r;
    }
}

// ---------------------------------------------------------------------------
// Kernel 8: init output with bias (for split-K atomic GEMM)
// ---------------------------------------------------------------------------
__global__ void init_out_kernel(float* __restrict__ out, const float* __restrict__ bout)
{
    int idx = blockIdx.x * blockDim.x + threadIdx.x;
    if (idx < NN * DIM) out[idx] = bout[idx % DIM];
}

// ---------------------------------------------------------------------------
extern "C" void kernel_launch(void* const* d_in, const int* in_sizes, int n_in,
                              void* d_out, int out_size)
{
    const float* x      = (const float*)d_in[0];
    const float* pairw  = (const float*)d_in[1];
    const float* rot    = (const float*)d_in[2];
    const float* trans  = (const float*)d_in[3];
    const float* Wsq    = (const float*)d_in[4];
    const float* Wsk    = (const float*)d_in[5];
    const float* Wsv    = (const float*)d_in[6];
    const float* Wpq    = (const float*)d_in[7];
    const float* Wpk    = (const float*)d_in[8];
    const float* Wpv    = (const float*)d_in[9];
    const float* pw     = (const float*)d_in[10];
    const float* Wpair  = (const float*)d_in[11];
    const float* bpair  = (const float*)d_in[12];
    const float* Wout   = (const float*)d_in[13];
    const float* bout   = (const float*)d_in[14];
    float* out = (float*)d_out;

    float *pWcat, *pProj, *pRes;
    cudaGetSymbolAddress((void**)&pWcat, g_Wcat);
    cudaGetSymbolAddress((void**)&pProj, g_proj);
    cudaGetSymbolAddress((void**)&pRes,  g_res);

    // 1. concat weights
    concat_w_kernel<<<(DIM * PROJ_COLS + 255) / 256, 256>>>(Wsq, Wsk, Wsv, Wpq, Wpk, Wpv);

    // 2. projections: proj[512,768] = x @ Wcat
    gemm64_kernel<<<dim3(PROJ_COLS / 64, NN / 64), 256>>>(x, pWcat, pProj,
                                                          NN, PROJ_COLS, DIM, DIM, 0);

    // 3. build QA/KB/vcombT
    transform_kernel<<<(H * NN) / 256, 256>>>(rot, trans, pw);

    // 4. QK logits (scalar + point) via K=32 GEMM -> g_lp
    logit_gemm_kernel<<<dim3(8, 8, 8), 256>>>();

    // 5. pair-bias logits + softmax fused (first pairwise stream) -> g_attn
    pair_logits_sm_kernel<<<NN, 256>>>(pairw, Wpair, bpair);

    // 6. AV GEMM (res_scalar + res_point + norms)
    av_kernel<<<dim3(8, 8), 256>>>(rot, trans);

    // 7. res_pair (second pairwise stream)
    res_pair_kernel<<<NN, 256>>>(pairw);

    // 8-9. out = res @ Wout + bout   (split-K=4, atomic)
    init_out_kernel<<<(NN * DIM + 255) / 256, 256>>>(out, bout);
    gemm64_kernel<<<dim3(DIM / 64, NN / 64, 4), 256>>>(pRes, Wout, out,
                                                       NN, DIM, RES_COLS, 352, 1);
}